// round 4
// baseline (speedup 1.0000x reference)
#include <cuda_runtime.h>
#include <math.h>

// ---------------- problem constants ----------------
#define B_ 256
#define T_ 500
#define I_ 8
#define H_ 1024
#define O_ 8
#define ALPHA_ 0.2f
#define NSTD_ 0.05f

// ---------------- persistent kernel geometry ----------------
#define GRID_ 128          // 8 batch-tiles x 16 j-tiles, all co-resident (<=148 SMs)
#define NTHR 128
#define BM 32              // batch tile
#define BN 64              // j tile
#define KB 64              // k tile
#define NKB (H_ / KB)      // 16

// smem layout (in floats)
#define MS_OFF 0
#define MS_SZ  (2 * KB * BN)          // 8192  (double-buffered M tile)
#define RS_OFF (MS_OFF + MS_SZ)
#define RS_SZ  (2 * KB * BM)          // 4096  (double-buffered r tile)
#define XS_OFF (RS_OFF + RS_SZ)
#define XS_SZ  (BM * I_)              // 256
#define WI_OFF (XS_OFF + XS_SZ)
#define WI_SZ  (I_ * BN)              // 512
#define WO_OFF (WI_OFF + WI_SZ)
#define WO_SZ  (BN * O_)              // 512
#define SMEM_FLOATS (WO_OFF + WO_SZ)  // 13568
#define SMEM_BYTES  (SMEM_FLOATS * 4) // 54272

// ---------------- device scratch (no allocations) ----------------
__device__ float g_M[H_ * H_];          // M[k][j] = relu(g[k]) * effW[j][k]
__device__ float g_rA[H_ * B_];         // r buffers, TRANSPOSED layout [h][b]
__device__ float g_rB[H_ * B_];
__device__ float g_outp[2 * 16 * B_ * O_];  // per-jtile output partials, double buffered
__device__ float g_out0[O_];
__device__ unsigned g_bar;

__device__ __forceinline__ float softplus_f(float v) {
    // stable softplus, matches jax.nn.softplus (BETA=1)
    return fmaxf(v, 0.0f) + log1pf(expf(-fabsf(v)));
}

__device__ __forceinline__ void cp16(unsigned dst, const void* src) {
    asm volatile("cp.async.cg.shared.global [%0], [%1], 16;" :: "r"(dst), "l"(src));
}

// ---------------- setup kernels ----------------

__global__ void k_reset() { g_bar = 0u; }

__global__ void k_build_M(const float* __restrict__ wrec, const float* __restrict__ mwrec,
                          const float* __restrict__ refEI, const float* __restrict__ g) {
    int n = blockIdx.x * blockDim.x + threadIdx.x;   // n = j*H + k
    if (n >= H_ * H_) return;
    int j = n >> 10;
    int k = n & (H_ - 1);
    float ei = refEI[k];               // row 0 of refEI = ei (exactly +/-1)
    float w  = wrec[n];                // wrec[j][k]
    // effW[j][k] = relu(w*ei)*ei*mwrec   (|ei|-1 term vanishes exactly)
    float e = fmaxf(w * ei, 0.0f) * ei * mwrec[n];
    g_M[k * H_ + j] = fmaxf(g[k], 0.0f) * e;
}

__global__ void k_init_r(const float* __restrict__ h0, const float* __restrict__ bvec) {
    int n = blockIdx.x * blockDim.x + threadIdx.x;   // layout [h][b]
    if (n >= H_ * B_) return;
    int hh = n >> 8;                                  // B_ = 256
    g_rA[n] = softplus_f(h0[hh] + bvec[hh]);
}

__global__ void k_out0(const float* __restrict__ h0, const float* __restrict__ bvec,
                       const float* __restrict__ wout) {
    int tid = threadIdx.x;
    float p[O_];
#pragma unroll
    for (int o = 0; o < O_; ++o) p[o] = 0.0f;
    for (int hh = tid; hh < H_; hh += 256) {
        float r0 = softplus_f(h0[hh] + bvec[hh]);
#pragma unroll
        for (int o = 0; o < O_; ++o) p[o] += r0 * wout[hh * O_ + o];
    }
#pragma unroll
    for (int d = 16; d > 0; d >>= 1)
#pragma unroll
        for (int o = 0; o < O_; ++o) p[o] += __shfl_xor_sync(0xffffffffu, p[o], d);
    __shared__ float ws[8][O_];
    if ((tid & 31) == 0)
        for (int o = 0; o < O_; ++o) ws[tid >> 5][o] = p[o];
    __syncthreads();
    if (tid < O_) {
        float s = 0.0f;
        for (int w = 0; w < 8; ++w) s += ws[w][tid];
        g_out0[tid] = s;
    }
}

__global__ void k_fill0(float* __restrict__ out) {
    int n = blockIdx.x * blockDim.x + threadIdx.x;   // over B*O
    if (n >= B_ * O_) return;
    out[(size_t)(n >> 3) * (T_ * O_) + (n & 7)] = g_out0[n & 7];   // t = 0
}

// ---------------- persistent RNN kernel ----------------

__global__ void __launch_bounds__(NTHR, 1)
k_rnn(const float* __restrict__ x, const float* __restrict__ noise,
      const float* __restrict__ wi, const float* __restrict__ wout,
      const float* __restrict__ bvec, const float* __restrict__ h0,
      float* __restrict__ out)
{
    extern __shared__ float sm[];
    float* Ms    = sm + MS_OFF;
    float* Rs    = sm + RS_OFF;
    float* Xs    = sm + XS_OFF;
    float* Wis   = sm + WI_OFF;
    float* Wouts = sm + WO_OFF;

    const int tid   = threadIdx.x;
    const int cta   = blockIdx.x;
    const int btile = cta >> 4;          // 0..7
    const int jtile = cta & 15;          // 0..15
    const int b0 = btile * BM;
    const int j0 = jtile * BN;
    const int jq = tid & 15;             // 16 j-quads -> 64 j
    const int bq = tid >> 4;             // 8 b-quads  -> 32 b
    const int myj = j0 + 4 * jq;
    const int myb = b0 + 4 * bq;

    // stage per-CTA constants
    for (int n = tid; n < I_ * BN; n += NTHR)
        Wis[n] = wi[(n >> 6) * H_ + j0 + (n & 63)];
    for (int n = tid; n < BN * O_; n += NTHR)
        Wouts[n] = wout[(j0 + (n >> 3)) * O_ + (n & 7)];

    float bT[4], h[4][4];
#pragma unroll
    for (int jj = 0; jj < 4; ++jj) {
        bT[jj] = bvec[myj + jj];
        float hv = h0[myj + jj];
#pragma unroll
        for (int bb = 0; bb < 4; ++bb) h[bb][jj] = hv;
    }
    __syncthreads();

    const unsigned ms_sh = (unsigned)__cvta_generic_to_shared(Ms);
    const unsigned rs_sh = (unsigned)__cvta_generic_to_shared(Rs);
    const unsigned xs_sh = (unsigned)__cvta_generic_to_shared(Xs);

    unsigned epoch = 0;

    for (int t = 0; t < T_ - 1; ++t) {
        const float* __restrict__ Rg = (t & 1) ? g_rB : g_rA;
        float* __restrict__       Rn = (t & 1) ? g_rA : g_rB;

        // ---- prologue: kb=0 tiles in flight ----
        {
#pragma unroll
            for (int p = 0; p < 8; ++p) {
                int c = p * NTHR + tid;
                int k = c >> 4, jv = c & 15;
                cp16(ms_sh + ((unsigned)(k * BN + 4 * jv) << 2),
                     g_M + (size_t)k * H_ + j0 + 4 * jv);
            }
#pragma unroll
            for (int p = 0; p < 4; ++p) {
                int c = p * NTHR + tid;
                int k = c >> 3, bv = c & 7;
                cp16(rs_sh + ((unsigned)(k * BM + 4 * bv) << 2),
                     Rg + (size_t)k * B_ + b0 + 4 * bv);
            }
            asm volatile("cp.async.commit_group;" ::: "memory");
        }

        // ---- noise prefetch into registers (DRAM latency hidden under GEMM) ----
        float4 nz[4];
#pragma unroll
        for (int bb = 0; bb < 4; ++bb)
            nz[bb] = __ldcg((const float4*)(noise +
                     (size_t)(myb + bb) * (T_ * H_) + (size_t)t * H_ + myj));

        // ---- deterministic reduce of PREVIOUS step's output partials ----
        if (t >= 1 && tid < 16) {
            int P = cta * 16 + tid;                       // P = b*8 + o, 0..2047
            const float* src = g_outp + (size_t)((t - 1) & 1) * (16 * B_ * O_);
            float s = 0.0f;
#pragma unroll
            for (int jt = 0; jt < 16; ++jt) s += __ldcv(src + jt * (B_ * O_) + P);
            out[(size_t)(P >> 3) * (T_ * O_) + (size_t)t * O_ + (P & 7)] = s;
        }

        float acc[4][4];
#pragma unroll
        for (int bb = 0; bb < 4; ++bb)
#pragma unroll
            for (int jj = 0; jj < 4; ++jj) acc[bb][jj] = 0.0f;

        // ---- main GEMM: acc[b][j] += r[k][b] * M[k][j] over k=0..1023 ----
#pragma unroll 1
        for (int kb = 0; kb < NKB; ++kb) {
            asm volatile("cp.async.wait_group 0;" ::: "memory");
            __syncthreads();   // kb's data visible; everyone done with kb-1's buffer
            const int buf = kb & 1;
            if (kb + 1 < NKB) {
                const int nb = buf ^ 1;
                const int k0 = (kb + 1) * KB;
#pragma unroll
                for (int p = 0; p < 8; ++p) {
                    int c = p * NTHR + tid;
                    int k = c >> 4, jv = c & 15;
                    cp16(ms_sh + ((unsigned)(nb * KB * BN + k * BN + 4 * jv) << 2),
                         g_M + (size_t)(k0 + k) * H_ + j0 + 4 * jv);
                }
#pragma unroll
                for (int p = 0; p < 4; ++p) {
                    int c = p * NTHR + tid;
                    int k = c >> 3, bv = c & 7;
                    cp16(rs_sh + ((unsigned)(nb * KB * BM + k * BM + 4 * bv) << 2),
                         Rg + (size_t)(k0 + k) * B_ + b0 + 4 * bv);
                }
                if (kb == 0 && tid < 64) {   // x prefetch rides along in this group
                    int bl = tid >> 1, hf = tid & 1;
                    cp16(xs_sh + ((unsigned)(bl * I_ + 4 * hf) << 2),
                         x + (size_t)(b0 + bl) * (T_ * I_) + (size_t)t * I_ + 4 * hf);
                }
                asm volatile("cp.async.commit_group;" ::: "memory");
            }

            const float* Mb = Ms + buf * (KB * BN) + 4 * jq;
            const float* Rb = Rs + buf * (KB * BM) + 4 * bq;
#pragma unroll 8
            for (int k = 0; k < KB; ++k) {
                float4 r4 = *(const float4*)(Rb + k * BM);
                float4 m4 = *(const float4*)(Mb + k * BN);
                acc[0][0] += r4.x * m4.x; acc[0][1] += r4.x * m4.y;
                acc[0][2] += r4.x * m4.z; acc[0][3] += r4.x * m4.w;
                acc[1][0] += r4.y * m4.x; acc[1][1] += r4.y * m4.y;
                acc[1][2] += r4.y * m4.z; acc[1][3] += r4.y * m4.w;
                acc[2][0] += r4.z * m4.x; acc[2][1] += r4.z * m4.y;
                acc[2][2] += r4.z * m4.z; acc[2][3] += r4.z * m4.w;
                acc[3][0] += r4.w * m4.x; acc[3][1] += r4.w * m4.y;
                acc[3][2] += r4.w * m4.z; acc[3][3] += r4.w * m4.w;
            }
            // no trailing sync needed: next iteration's wait+sync precedes buffer reuse
        }

        // ---- input projection: inp[b][j] = sum_i x[b,t,i] * wi[i,j] ----
        float inp[4][4];
#pragma unroll
        for (int bb = 0; bb < 4; ++bb)
#pragma unroll
            for (int jj = 0; jj < 4; ++jj) inp[bb][jj] = 0.0f;
#pragma unroll
        for (int i = 0; i < I_; ++i) {
            float4 w4 = *(const float4*)(Wis + i * BN + 4 * jq);
#pragma unroll
            for (int bb = 0; bb < 4; ++bb) {
                float xv = Xs[(4 * bq + bb) * I_ + i];
                inp[bb][0] += xv * w4.x; inp[bb][1] += xv * w4.y;
                inp[bb][2] += xv * w4.z; inp[bb][3] += xv * w4.w;
            }
        }

        // ---- state update + softplus ----
        float rnew[4][4];
#pragma unroll
        for (int bb = 0; bb < 4; ++bb) {
            const float* nzv = &nz[bb].x;
#pragma unroll
            for (int jj = 0; jj < 4; ++jj) {
                float hv = h[bb][jj];
                hv = hv + NSTD_ * nzv[jj] + ALPHA_ * (-hv + acc[bb][jj] + inp[bb][jj]);
                h[bb][jj] = hv;
                rnew[bb][jj] = softplus_f(hv + bT[jj]);
            }
        }

        // ---- write r transposed [j][b] for next step ----
#pragma unroll
        for (int jj = 0; jj < 4; ++jj) {
            float4 v = make_float4(rnew[0][jj], rnew[1][jj], rnew[2][jj], rnew[3][jj]);
            *(float4*)(Rn + (size_t)(myj + jj) * B_ + myb) = v;
        }

        // ---- output partials: p[b][o] = sum_{local j} rnew * wout ----
        float p[4][8];
#pragma unroll
        for (int bb = 0; bb < 4; ++bb)
#pragma unroll
            for (int o = 0; o < 8; ++o) p[bb][o] = 0.0f;
#pragma unroll
        for (int jj = 0; jj < 4; ++jj) {
            float4 wo0 = *(const float4*)(Wouts + (4 * jq + jj) * O_);
            float4 wo1 = *(const float4*)(Wouts + (4 * jq + jj) * O_ + 4);
#pragma unroll
            for (int bb = 0; bb < 4; ++bb) {
                float rv = rnew[bb][jj];
                p[bb][0] += rv * wo0.x; p[bb][1] += rv * wo0.y;
                p[bb][2] += rv * wo0.z; p[bb][3] += rv * wo0.w;
                p[bb][4] += rv * wo1.x; p[bb][5] += rv * wo1.y;
                p[bb][6] += rv * wo1.z; p[bb][7] += rv * wo1.w;
            }
        }
        // reduce across the 16 jq lanes (stays inside each 16-lane half-warp)
#pragma unroll
        for (int off = 8; off >= 1; off >>= 1)
#pragma unroll
            for (int bb = 0; bb < 4; ++bb)
#pragma unroll
                for (int o = 0; o < 8; ++o)
                    p[bb][o] += __shfl_xor_sync(0xffffffffu, p[bb][o], off);
        if (jq == 0) {
            float* dst = g_outp + (size_t)(t & 1) * (16 * B_ * O_)
                       + (size_t)jtile * (B_ * O_) + (size_t)myb * O_;
#pragma unroll
            for (int bb = 0; bb < 4; ++bb) {
                *(float4*)(dst + bb * O_)     = make_float4(p[bb][0], p[bb][1], p[bb][2], p[bb][3]);
                *(float4*)(dst + bb * O_ + 4) = make_float4(p[bb][4], p[bb][5], p[bb][6], p[bb][7]);
            }
        }

        // ---- grid barrier ----
        epoch++;
        __syncthreads();
        if (tid == 0) {
            __threadfence();
            atomicAdd(&g_bar, 1u);
            const unsigned target = epoch * GRID_;
            while (*(volatile unsigned*)&g_bar < target) __nanosleep(32);
        }
        __syncthreads();
    }

    // ---- final output reduce (step T-2 -> out[:, T-1, :]) ----
    if (tid < 16) {
        int P = cta * 16 + tid;
        const float* src = g_outp + (size_t)((T_ - 2) & 1) * (16 * B_ * O_);
        float s = 0.0f;
#pragma unroll
        for (int jt = 0; jt < 16; ++jt) s += __ldcv(src + jt * (B_ * O_) + P);
        out[(size_t)(P >> 3) * (T_ * O_) + (size_t)(T_ - 1) * O_ + (P & 7)] = s;
    }
}

// ---------------- launch ----------------

extern "C" void kernel_launch(void* const* d_in, const int* in_sizes, int n_in,
                              void* d_out, int out_size) {
    const float* x     = (const float*)d_in[0];
    const float* noise = (const float*)d_in[1];
    const float* wi    = (const float*)d_in[2];
    const float* wrec  = (const float*)d_in[3];
    const float* wout  = (const float*)d_in[4];
    const float* bvec  = (const float*)d_in[5];
    const float* g     = (const float*)d_in[6];
    const float* h0    = (const float*)d_in[7];
    const float* refEI = (const float*)d_in[8];
    const float* mwrec = (const float*)d_in[9];
    float* out = (float*)d_out;

    cudaFuncSetAttribute(k_rnn, cudaFuncAttributeMaxDynamicSharedMemorySize, SMEM_BYTES);

    k_reset<<<1, 1>>>();
    k_build_M<<<(H_ * H_ + 255) / 256, 256>>>(wrec, mwrec, refEI, g);
    k_init_r<<<(H_ * B_ + 255) / 256, 256>>>(h0, bvec);
    k_out0<<<1, 256>>>(h0, bvec, wout);
    k_fill0<<<(B_ * O_ + 255) / 256, 256>>>(out);
    k_rnn<<<GRID_, NTHR, SMEM_BYTES>>>(x, noise, wi, wout, bvec, h0, out);
}